// round 16
// baseline (speedup 1.0000x reference)
#include <cuda_runtime.h>
#include <cuda_fp16.h>
#include <math.h>

#define NA 120            // angles
#define LL 91             // padded canvas size / detector bins
#define NS 64             // slices
#define QW 65             // quad-tap array extent per axis (dp,wp in [0,64])
#define NRAYS (NA * LL)   // 10920
#define RPB 8             // rays per CTA (one warp per ray)
#define NBLK  (NRAYS / RPB)   // 1365
#define MAXK 96           // per-ray sample slots, padded to multiple of 8
#define SCALE 4294967296.0    // 2^32 fixed-point scale

// Quad-tap array in fp16: g_qh[(dp*QW+wp)*NS+s] = half4(v[dp][wp], v[dp][wp+1],
// v[dp+1][wp], v[dp+1][wp+1]) packed as uint2 (8 bytes). v is the zero-padded
// transposed diff image (v[r][c] = diff(r-1, c-1)).
__device__ uint2 g_qh[QW * QW * NS];
// Input-independent per-sample meta: (w00w01 half2, w10w11 half2, byte off, 0).
__device__ uint4 g_meta[NRAYS * MAXK];          // 16.8 MB
__device__ int   g_cnt[NRAYS];                  // padded sample count per ray
// Fixed-point global accumulator + completion ticket (zero-initialized at load;
// the last k_radon CTA resets them, so graph replays stay correct).
__device__ unsigned long long g_total;
__device__ unsigned int g_done;

static __device__ __forceinline__ __half2 u2h(unsigned int u) {
    return *reinterpret_cast<__half2*>(&u);
}

// Kernel 1a: fused diff + transpose + quad-tap build (fp16 output).
// Grid 65*4: blockIdx = dp*4 + s-chunk (16 slices per chunk).
__global__ void __launch_bounds__(256) k_build(const float* __restrict__ a,
                                               const float* __restrict__ b) {
    __shared__ float tile[2][16][67];   // [plane][s-local][padded col]
    int dp = blockIdx.x >> 2;
    int sc = blockIdx.x & 3;
    int s0 = sc * 16;

    for (int k = threadIdx.x; k < 2 * 16 * 67; k += 256)
        ((float*)tile)[k] = 0.0f;
    __syncthreads();

    #pragma unroll
    for (int p = 0; p < 2; ++p) {
        int d = dp - 1 + p;
        if (d >= 0 && d < 64) {
            const float* pa = a + d * 4096 + s0 * 64;
            const float* pb = b + d * 4096 + s0 * 64;
            for (int k = threadIdx.x; k < 16 * 64; k += 256)   // k = sl*64 + w
                tile[p][k >> 6][(k & 63) + 1] = pa[k] - pb[k];
        }
    }
    __syncthreads();

    for (int k = threadIdx.x; k < QW * 16; k += 256) {         // k = wp*16 + sl
        int wp = k >> 4, sl = k & 15;
        __half2 lo = __floats2half2_rn(tile[0][sl][wp], tile[0][sl][wp + 1]);
        __half2 hi = __floats2half2_rn(tile[1][sl][wp], tile[1][sl][wp + 1]);
        uint2 u;
        u.x = *(const unsigned int*)&lo;
        u.y = *(const unsigned int*)&hi;
        g_qh[(dp * QW + wp) * NS + s0 + sl] = u;
    }
}

// Kernel 1b: input-independent meta table. One thread per (ray, slot).
// NRAYS*MAXK = 1048320 = 4095 * 256 exactly.
__global__ void __launch_bounds__(256) k_meta() {
    int idx = blockIdx.x * 256 + threadIdx.x;
    int ray = idx / MAXK;
    int ir  = idx - ray * MAXK;
    int a   = ray / LL;
    int j   = ray - a * LL;

    // theta = a * (120/119) degrees (jnp.linspace(0,120,120) * pi/180)
    float theta = (float)a * (float)(120.0 / 119.0 * 3.14159265358979323846 / 180.0);
    float cth, sth;
    sincosf(theta, &sth, &cth);
    float uj = (float)(j - 45);
    float Cx = fmaf(cth, uj, 32.0f) + 45.0f * sth;   // ix = Cx - sth*i
    float Cy = fmaf(sth, uj, 32.0f) - 45.0f * cth;   // iy = Cy + cth*i

    // Analytic active range, widened by 1 each side; per-sample exact bounds
    // check below guards any fast-division rounding.
    int ilo = 0, ihi = LL;
    {
        float D = -sth, C = Cx;
        if (fabsf(D) > 1e-6f) {
            float r1 = __fdividef(-1.0f - C, D), r2 = __fdividef(64.0f - C, D);
            float lo = fminf(r1, r2), hi = fmaxf(r1, r2);
            ilo = max(ilo, (int)ceilf(lo) - 1);
            ihi = min(ihi, (int)floorf(hi) + 2);
        } else if (C <= -1.0f || C >= 64.0f) ihi = ilo;
    }
    {
        float D = cth, C = Cy;
        if (fabsf(D) > 1e-6f) {
            float r1 = __fdividef(-1.0f - C, D), r2 = __fdividef(64.0f - C, D);
            float lo = fminf(r1, r2), hi = fmaxf(r1, r2);
            ilo = max(ilo, (int)ceilf(lo) - 1);
            ihi = min(ihi, (int)floorf(hi) + 2);
        } else if (C <= -1.0f || C >= 64.0f) ihi = ilo;
    }
    ilo = max(ilo, 0);
    ihi = min(ihi, LL);
    int cnt = max(ihi - ilo, 0);

    if (ir == 0) g_cnt[ray] = (cnt + 7) & ~7;   // padded count

    uint4 m = make_uint4(0u, 0u, 0u, 0u);
    if (ir < cnt) {
        int i = ilo + ir;
        float fi = (float)i;
        float ix = fmaf(-sth, fi, Cx);
        float iy = fmaf( cth, fi, Cy);
        if (ix > -1.0f && ix < 64.0f && iy > -1.0f && iy < 64.0f) {
            float fw = floorf(ix), fd = floorf(iy);
            int   w0 = (int)fw,    d0 = (int)fd;    // in [-1, 63]
            float fx = ix - fw,    fy = iy - fd;
            float w11 = fx * fy;
            float w00 = 1.0f - fx - fy + w11;
            float w01 = fx - w11;
            float w10 = fy - w11;
            __half2 lo = __floats2half2_rn(w00, w01);
            __half2 hi = __floats2half2_rn(w10, w11);
            m.x = *(const unsigned int*)&lo;
            m.y = *(const unsigned int*)&hi;
            m.z = (unsigned int)(((d0 + 1) * QW + (w0 + 1)) * (NS * 8));
        }
    }
    g_meta[idx] = m;
}

// Kernel 2: pure accumulate. Warp = ray, lane = slice pair; no barriers until
// the final CTA reduction. Inner step: uniform LDG.128 (meta) + LDG.128 (data)
// + 4 HFMA2 covering 2 slice-samples.
__global__ void __launch_bounds__(256) k_radon(float* __restrict__ d_out) {
    __shared__ float s_red[RPB];

    int tid  = threadIdx.x;
    int lane = tid & 31;
    int sub  = tid >> 5;
    int ray  = blockIdx.x * RPB + sub;

    int cntp = __ldg(&g_cnt[ray]);
    const uint4* mp  = &g_meta[ray * MAXK];
    const char* base = (const char*)g_qh + lane * 16;

    float accA = 0.0f, accB = 0.0f;   // fp32 per-slice integrals (2 slices/lane)
    for (int k0 = 0; k0 < cntp; k0 += 8) {
        __half2 z = __float2half2_rn(0.0f);
        __half2 h0 = z, h1 = z, h2 = z, h3 = z;
        #pragma unroll
        for (int k = 0; k < 8; ++k) {
            uint4 m = __ldg(mp + k0 + k);                // LDG.128 uniform (broadcast)
            uint4 u = *(const uint4*)(base + m.z);       // LDG.128 coalesced
            h0 = __hfma2(u2h(m.x), u2h(u.x), h0);        // slice A: v00,v01
            h1 = __hfma2(u2h(m.y), u2h(u.y), h1);        // slice A: v10,v11
            h2 = __hfma2(u2h(m.x), u2h(u.z), h2);        // slice B: v00,v01
            h3 = __hfma2(u2h(m.y), u2h(u.w), h3);        // slice B: v10,v11
        }
        float2 f;
        f = __half22float2(h0); accA += f.x + f.y;
        f = __half22float2(h1); accA += f.x + f.y;
        f = __half22float2(h2); accB += f.x + f.y;
        f = __half22float2(h3); accB += f.x + f.y;
    }

    // |integral| per slice, reduce over the warp (= over 64 slices of the ray).
    float val = fabsf(accA) + fabsf(accB);
    #pragma unroll
    for (int off = 16; off; off >>= 1)
        val += __shfl_down_sync(0xffffffffu, val, off);

    if (lane == 0) s_red[sub] = val;
    __syncthreads();

    if (tid == 0) {
        double tot = 0.0;
        #pragma unroll
        for (int k = 0; k < RPB; ++k) tot += (double)s_red[k];
        unsigned long long q = (unsigned long long)(tot * SCALE);
        atomicAdd(&g_total, q);
        __threadfence();
        unsigned int old = atomicAdd(&g_done, 1u);
        if (old == NBLK - 1) {
            unsigned long long total = atomicAdd(&g_total, 0ULL);  // fenced read
            d_out[0] = (float)((double)total * (1.0 / SCALE) / (double)NRAYS);
            g_total = 0ULL;   // reset for next graph replay
            g_done  = 0u;
        }
    }
}

extern "C" void kernel_launch(void* const* d_in, const int* in_sizes, int n_in,
                              void* d_out, int out_size) {
    const float* v_out = (const float*)d_in[0];
    const float* v_gt  = (const float*)d_in[1];

    k_meta<<<(NRAYS * MAXK) / 256, 256>>>();
    k_build<<<QW * 4, 256>>>(v_out, v_gt);
    k_radon<<<NBLK, 256>>>((float*)d_out);
}

// round 17
// speedup vs baseline: 1.3868x; 1.3868x over previous
#include <cuda_runtime.h>
#include <cuda_fp16.h>
#include <math.h>

#define NA 120            // angles
#define LL 91             // padded canvas size / detector bins
#define NS 64             // slices
#define QW 65             // quad-tap array extent per axis (dp,wp in [0,64])
#define NRAYS (NA * LL)   // 10920
#define RPB 8             // rays per CTA (one warp per ray)
#define NBLK  (NRAYS / RPB)   // 1365
#define MAXK 96           // per-ray sample slots, padded to multiple of 8
#define SCALE 4294967296.0    // 2^32 fixed-point scale

// Quad-tap array in fp16: g_qh[(dp*QW+wp)*NS+s] = half4(v[dp][wp], v[dp][wp+1],
// v[dp+1][wp], v[dp+1][wp+1]) packed as uint2 (8 bytes). v is the zero-padded
// transposed diff image (v[r][c] = diff(r-1, c-1)).
__device__ uint2 g_qh[QW * QW * NS];
// Fixed-point global accumulator + completion ticket (zero-initialized at load;
// the last k_radon CTA resets them, so graph replays stay correct).
__device__ unsigned long long g_total;
__device__ unsigned int g_done;

static __device__ __forceinline__ __half2 u2h(unsigned int u) {
    return *reinterpret_cast<__half2*>(&u);
}

// Kernel 1: fused diff + transpose + quad-tap build (fp16 output).
// Grid 65*4: blockIdx = dp*4 + s-chunk (16 slices per chunk).
__global__ void __launch_bounds__(256) k_build(const float* __restrict__ a,
                                               const float* __restrict__ b) {
    __shared__ float tile[2][16][67];   // [plane][s-local][padded col]
    int dp = blockIdx.x >> 2;
    int sc = blockIdx.x & 3;
    int s0 = sc * 16;

    for (int k = threadIdx.x; k < 2 * 16 * 67; k += 256)
        ((float*)tile)[k] = 0.0f;
    __syncthreads();

    #pragma unroll
    for (int p = 0; p < 2; ++p) {
        int d = dp - 1 + p;
        if (d >= 0 && d < 64) {
            const float* pa = a + d * 4096 + s0 * 64;
            const float* pb = b + d * 4096 + s0 * 64;
            for (int k = threadIdx.x; k < 16 * 64; k += 256)   // k = sl*64 + w
                tile[p][k >> 6][(k & 63) + 1] = pa[k] - pb[k];
        }
    }
    __syncthreads();

    for (int k = threadIdx.x; k < QW * 16; k += 256) {         // k = wp*16 + sl
        int wp = k >> 4, sl = k & 15;
        __half2 lo = __floats2half2_rn(tile[0][sl][wp], tile[0][sl][wp + 1]);
        __half2 hi = __floats2half2_rn(tile[1][sl][wp], tile[1][sl][wp + 1]);
        uint2 u;
        u.x = *(const unsigned int*)&lo;
        u.y = *(const unsigned int*)&hi;
        g_qh[(dp * QW + wp) * NS + s0 + sl] = u;
    }
}

// Kernel 2: 8 rays per CTA, one warp per ray, FULLY warp-autonomous:
// every lane redundantly computes its ray's params; each lane fills 3 of the
// 96 smem meta slots; __syncwarp only, no block barrier until the reduction.
// Phase 2: LDS.128 (meta) + LDG.128 (data) + 4 HFMA2 per 2 slice-samples.
__global__ void __launch_bounds__(256) k_radon(float* __restrict__ d_out) {
    __shared__ uint4  s_meta[RPB][MAXK];   // (w00w01 h2, w10w11 h2, byte off, 0)
    __shared__ float  s_red[RPB];

    int tid  = threadIdx.x;
    int lane = tid & 31;
    int sub  = tid >> 5;                   // warp = ray-within-block
    int ray  = blockIdx.x * RPB + sub;
    int a    = ray / LL;
    int j    = ray - a * LL;

    // ---- Phase 0 (all lanes, redundant): ray params + analytic range ----
    float theta = (float)a * (float)(120.0 / 119.0 * 3.14159265358979323846 / 180.0);
    float cth, sth;
    sincosf(theta, &sth, &cth);
    float uj = (float)(j - 45);
    float Cx = fmaf(cth, uj, 32.0f) + 45.0f * sth;   // ix = Cx - sth*i
    float Cy = fmaf(sth, uj, 32.0f) - 45.0f * cth;   // iy = Cy + cth*i

    // Range widened by 1 each side; exact per-sample bounds check below guards
    // fast-division rounding.
    int ilo = 0, ihi = LL;
    {
        float D = -sth, C = Cx;
        if (fabsf(D) > 1e-6f) {
            float r1 = __fdividef(-1.0f - C, D), r2 = __fdividef(64.0f - C, D);
            float lo = fminf(r1, r2), hi = fmaxf(r1, r2);
            ilo = max(ilo, (int)ceilf(lo) - 1);
            ihi = min(ihi, (int)floorf(hi) + 2);
        } else if (C <= -1.0f || C >= 64.0f) ihi = ilo;
    }
    {
        float D = cth, C = Cy;
        if (fabsf(D) > 1e-6f) {
            float r1 = __fdividef(-1.0f - C, D), r2 = __fdividef(64.0f - C, D);
            float lo = fminf(r1, r2), hi = fmaxf(r1, r2);
            ilo = max(ilo, (int)ceilf(lo) - 1);
            ihi = min(ihi, (int)floorf(hi) + 2);
        } else if (C <= -1.0f || C >= 64.0f) ihi = ilo;
    }
    ilo = max(ilo, 0);
    ihi = min(ihi, LL);
    int cnt  = max(ihi - ilo, 0);
    int cntp = (cnt + 7) & ~7;             // padded count (<= 96)

    // ---- Phase 1 (per-warp): each lane fills slots lane, lane+32, lane+64 ----
    #pragma unroll
    for (int ir = lane; ir < MAXK; ir += 32) {
        uint4 m = make_uint4(0u, 0u, 0u, 0u);
        if (ir < cnt) {
            float fi = (float)(ilo + ir);
            float ix = fmaf(-sth, fi, Cx);
            float iy = fmaf( cth, fi, Cy);
            if (ix > -1.0f && ix < 64.0f && iy > -1.0f && iy < 64.0f) {
                float fw = floorf(ix), fd = floorf(iy);
                int   w0 = (int)fw,    d0 = (int)fd;    // in [-1, 63]
                float fx = ix - fw,    fy = iy - fd;
                float w11 = fx * fy;
                float w00 = 1.0f - fx - fy + w11;
                float w01 = fx - w11;
                float w10 = fy - w11;
                __half2 lo = __floats2half2_rn(w00, w01);
                __half2 hi = __floats2half2_rn(w10, w11);
                m.x = *(const unsigned int*)&lo;
                m.y = *(const unsigned int*)&hi;
                m.z = (unsigned int)(((d0 + 1) * QW + (w0 + 1)) * (NS * 8));
            }
        }
        s_meta[sub][ir] = m;
    }
    __syncwarp();

    // ---- Phase 2: lane = slice pair (s = 2*lane, 2*lane+1) ----
    const char* base = (const char*)g_qh + lane * 16;

    float accA = 0.0f, accB = 0.0f;        // fp32 per-slice integrals
    for (int k0 = 0; k0 < cntp; k0 += 8) {
        __half2 z = __float2half2_rn(0.0f);
        __half2 h0 = z, h1 = z, h2 = z, h3 = z;
        #pragma unroll
        for (int k = 0; k < 8; ++k) {
            uint4 m = s_meta[sub][k0 + k];               // LDS.128 (warp-uniform)
            uint4 u = *(const uint4*)(base + m.z);       // LDG.128 coalesced
            h0 = __hfma2(u2h(m.x), u2h(u.x), h0);        // slice A: v00,v01
            h1 = __hfma2(u2h(m.y), u2h(u.y), h1);        // slice A: v10,v11
            h2 = __hfma2(u2h(m.x), u2h(u.z), h2);        // slice B: v00,v01
            h3 = __hfma2(u2h(m.y), u2h(u.w), h3);        // slice B: v10,v11
        }
        float2 f;
        f = __half22float2(h0); accA += f.x + f.y;
        f = __half22float2(h1); accA += f.x + f.y;
        f = __half22float2(h2); accB += f.x + f.y;
        f = __half22float2(h3); accB += f.x + f.y;
    }

    // |integral| per slice, reduce over the warp (= over 64 slices of the ray).
    float val = fabsf(accA) + fabsf(accB);
    #pragma unroll
    for (int off = 16; off; off >>= 1)
        val += __shfl_down_sync(0xffffffffu, val, off);

    if (lane == 0) s_red[sub] = val;
    __syncthreads();

    if (tid == 0) {
        double tot = 0.0;
        #pragma unroll
        for (int k = 0; k < RPB; ++k) tot += (double)s_red[k];
        unsigned long long q = (unsigned long long)(tot * SCALE);
        atomicAdd(&g_total, q);
        __threadfence();
        unsigned int old = atomicAdd(&g_done, 1u);
        if (old == NBLK - 1) {
            unsigned long long total = atomicAdd(&g_total, 0ULL);  // fenced read
            d_out[0] = (float)((double)total * (1.0 / SCALE) / (double)NRAYS);
            g_total = 0ULL;   // reset for next graph replay
            g_done  = 0u;
        }
    }
}

extern "C" void kernel_launch(void* const* d_in, const int* in_sizes, int n_in,
                              void* d_out, int out_size) {
    const float* v_out = (const float*)d_in[0];
    const float* v_gt  = (const float*)d_in[1];

    k_build<<<QW * 4, 256>>>(v_out, v_gt);
    k_radon<<<NBLK, 256>>>((float*)d_out);
}